// round 7
// baseline (speedup 1.0000x reference)
#include <cuda_runtime.h>
#include <cuda_fp16.h>
#include <math.h>

#define NNODES 50000
#define FIN    256
#define HH     4
#define HD     64
#define F1     (HH*HD)          // 256
#define EMAX   1600000
#define SLOPE  0.2f
#define FULLM  0xffffffffu

// ---------------- scratch (device globals) ----------------------------------
__device__ float  g_h1[(size_t)NNODES * F1];     // 51.2 MB (fp32, for alpha)
__device__ __half g_h1h[(size_t)NNODES * F1];    // 25.6 MB (fp16, for gather)
__device__ float  g_o1[(size_t)NNODES * F1];     // 51.2 MB
__device__ float  g_h2[(size_t)NNODES * HD];     // 12.8 MB
__device__ __half g_h2h[(size_t)NNODES * HD];    // 6.4 MB
__device__ float  g_as1[NNODES * HH];
__device__ float  g_ad1[NNODES * HH];
__device__ float  g_as2[NNODES];
__device__ float  g_ad2[NNODES];
__device__ int    g_deg[NNODES];
__device__ int    g_fill[NNODES];
__device__ int    g_roff[NNODES + 1];
__device__ int    g_csr_src[EMAX];               // 6.4 MB

// ---------------- fp16 mma helpers -------------------------------------------
__device__ __forceinline__ void mma_f16(float* c, const unsigned* a, const unsigned* b) {
    asm volatile(
        "mma.sync.aligned.m16n8k16.row.col.f32.f16.f16.f32 "
        "{%0,%1,%2,%3}, {%4,%5,%6,%7}, {%8,%9}, {%0,%1,%2,%3};"
        : "+f"(c[0]), "+f"(c[1]), "+f"(c[2]), "+f"(c[3])
        : "r"(a[0]), "r"(a[1]), "r"(a[2]), "r"(a[3]), "r"(b[0]), "r"(b[1]));
}

// ---- split-fp16 GEMM (≈fp32 accuracy): C[M,N]=A[M,K]@B[K,N], row-major ----
// Writes fp32 C and fp16 mirror C16. K % 32 == 0, N % BN == 0.
template<int BM, int BN, int WM, int WN>
__global__ void hgemm_split_kernel(const float* __restrict__ A,
                                   const float* __restrict__ B,
                                   float* __restrict__ C,
                                   __half* __restrict__ C16,
                                   int M, int N, int K)
{
    constexpr int BK = 32;
    constexpr int PAD = 8;
    constexpr int LDK = BK + PAD;        // 40 halves per row
    constexpr int WARPS_M = BM / WM;
    constexpr int WARPS_N = BN / WN;
    constexpr int THREADS = WARPS_M * WARPS_N * 32;
    constexpr int MT = WM / 16;
    constexpr int NT = WN / 8;

    __shared__ __half AsH[BM][LDK];
    __shared__ __half AsL[BM][LDK];
    __shared__ __half BsH[BN][LDK];      // transposed: [n][k]
    __shared__ __half BsL[BN][LDK];

    const int tid  = threadIdx.x;
    const int lane = tid & 31;
    const int wid  = tid >> 5;
    const int wm   = wid % WARPS_M;
    const int wn   = wid / WARPS_M;
    const int gid  = lane >> 2;          // 0..7
    const int tg   = lane & 3;           // 0..3
    const int row0 = blockIdx.y * BM;
    const int col0 = blockIdx.x * BN;

    float acc[MT][NT][4];
#pragma unroll
    for (int i = 0; i < MT; i++)
#pragma unroll
        for (int j = 0; j < NT; j++)
#pragma unroll
            for (int r = 0; r < 4; r++) acc[i][j][r] = 0.f;

    for (int k0 = 0; k0 < K; k0 += BK) {
        // ---- stage A tile (BM x BK): split fp32 -> hi/lo halves ----
#pragma unroll
        for (int i = tid; i < BM * (BK / 4); i += THREADS) {
            int m  = i / (BK / 4);
            int kq = (i % (BK / 4)) * 4;
            float4 v = make_float4(0.f, 0.f, 0.f, 0.f);
            if (row0 + m < M)
                v = *(const float4*)&A[(size_t)(row0 + m) * K + k0 + kq];
            float f[4] = {v.x, v.y, v.z, v.w};
            __half hi[4], lo[4];
#pragma unroll
            for (int j = 0; j < 4; j++) {
                hi[j] = __float2half_rn(f[j]);
                lo[j] = __float2half_rn(f[j] - __half2float(hi[j]));
            }
            *(__half2*)&AsH[m][kq]     = __halves2half2(hi[0], hi[1]);
            *(__half2*)&AsH[m][kq + 2] = __halves2half2(hi[2], hi[3]);
            *(__half2*)&AsL[m][kq]     = __halves2half2(lo[0], lo[1]);
            *(__half2*)&AsL[m][kq + 2] = __halves2half2(lo[2], lo[3]);
        }
        // ---- stage B tile (BK x BN), transposed into [n][k] ----
#pragma unroll
        for (int i = tid; i < BK * (BN / 4); i += THREADS) {
            int kk = i / (BN / 4);
            int nq = (i % (BN / 4)) * 4;
            float4 v = *(const float4*)&B[(size_t)(k0 + kk) * N + col0 + nq];
            float f[4] = {v.x, v.y, v.z, v.w};
#pragma unroll
            for (int j = 0; j < 4; j++) {
                __half hi = __float2half_rn(f[j]);
                BsH[nq + j][kk] = hi;
                BsL[nq + j][kk] = __float2half_rn(f[j] - __half2float(hi));
            }
        }
        __syncthreads();

#pragma unroll
        for (int ks = 0; ks < BK / 16; ks++) {
            const int kb = ks * 16;
            unsigned aH[MT][4], aL[MT][4], bH[NT][2], bL[NT][2];
#pragma unroll
            for (int mt = 0; mt < MT; mt++) {
                int mr = wm * WM + mt * 16 + gid;
                aH[mt][0] = *(const unsigned*)&AsH[mr    ][kb + 2 * tg];
                aH[mt][1] = *(const unsigned*)&AsH[mr + 8][kb + 2 * tg];
                aH[mt][2] = *(const unsigned*)&AsH[mr    ][kb + 2 * tg + 8];
                aH[mt][3] = *(const unsigned*)&AsH[mr + 8][kb + 2 * tg + 8];
                aL[mt][0] = *(const unsigned*)&AsL[mr    ][kb + 2 * tg];
                aL[mt][1] = *(const unsigned*)&AsL[mr + 8][kb + 2 * tg];
                aL[mt][2] = *(const unsigned*)&AsL[mr    ][kb + 2 * tg + 8];
                aL[mt][3] = *(const unsigned*)&AsL[mr + 8][kb + 2 * tg + 8];
            }
#pragma unroll
            for (int nt = 0; nt < NT; nt++) {
                int nc = wn * WN + nt * 8 + gid;
                bH[nt][0] = *(const unsigned*)&BsH[nc][kb + 2 * tg];
                bH[nt][1] = *(const unsigned*)&BsH[nc][kb + 2 * tg + 8];
                bL[nt][0] = *(const unsigned*)&BsL[nc][kb + 2 * tg];
                bL[nt][1] = *(const unsigned*)&BsL[nc][kb + 2 * tg + 8];
            }
#pragma unroll
            for (int mt = 0; mt < MT; mt++)
#pragma unroll
                for (int nt = 0; nt < NT; nt++) {
                    mma_f16(acc[mt][nt], aH[mt], bH[nt]);
                    mma_f16(acc[mt][nt], aH[mt], bL[nt]);
                    mma_f16(acc[mt][nt], aL[mt], bH[nt]);
                }
        }
        __syncthreads();
    }

    // ---- epilogue ----
#pragma unroll
    for (int mt = 0; mt < MT; mt++) {
        int m0 = row0 + wm * WM + mt * 16 + gid;
#pragma unroll
        for (int nt = 0; nt < NT; nt++) {
            int nc = col0 + wn * WN + nt * 8 + tg * 2;
            if (m0 < M) {
                *(float2*)&C[(size_t)m0 * N + nc] =
                    make_float2(acc[mt][nt][0], acc[mt][nt][1]);
                *(__half2*)&C16[(size_t)m0 * N + nc] =
                    __floats2half2_rn(acc[mt][nt][0], acc[mt][nt][1]);
            }
            if (m0 + 8 < M) {
                *(float2*)&C[(size_t)(m0 + 8) * N + nc] =
                    make_float2(acc[mt][nt][2], acc[mt][nt][3]);
                *(__half2*)&C16[(size_t)(m0 + 8) * N + nc] =
                    __floats2half2_rn(acc[mt][nt][2], acc[mt][nt][3]);
            }
        }
    }
}

// ---------------- CSR build -------------------------------------------------
__global__ void hist_kernel(const int* __restrict__ dst, int E, int* __restrict__ deg)
{
    int e = blockIdx.x * blockDim.x + threadIdx.x;
    if (e >= E) return;
    int d = dst[e];
    if ((unsigned)d < NNODES) atomicAdd(&deg[d], 1);
}

__global__ void scan_kernel(const int* __restrict__ deg, int* __restrict__ roff)
{
    __shared__ int part[1024];
    const int tid = threadIdx.x;
    const int CH = (NNODES + 1023) / 1024;
    const int base = tid * CH;
    int s = 0;
    for (int i = 0; i < CH; i++) {
        int idx = base + i;
        if (idx < NNODES) s += deg[idx];
    }
    part[tid] = s;
    __syncthreads();
    for (int off = 1; off < 1024; off <<= 1) {
        int v = 0;
        if (tid >= off) v = part[tid - off];
        __syncthreads();
        if (tid >= off) part[tid] += v;
        __syncthreads();
    }
    int run = (tid == 0) ? 0 : part[tid - 1];
    for (int i = 0; i < CH; i++) {
        int idx = base + i;
        if (idx < NNODES) { roff[idx] = run; run += deg[idx]; }
    }
    if (tid == 1023) roff[NNODES] = run;
}

__global__ void scatter_kernel(const int* __restrict__ src, const int* __restrict__ dst,
                               int E, const int* __restrict__ roff,
                               int* __restrict__ fill, int* __restrict__ csr)
{
    int e = blockIdx.x * blockDim.x + threadIdx.x;
    if (e >= E) return;
    int d = dst[e], s = src[e];
    if ((unsigned)d >= NNODES || (unsigned)s >= NNODES) return;
    int p = atomicAdd(&fill[d], 1);
    csr[roff[d] + p] = s;
}

// ---------------- per-node attention logits (fp32 h) ------------------------
__global__ void alpha_kernel(const float* __restrict__ h,
                             const float* __restrict__ a_src,
                             const float* __restrict__ a_dst,
                             float* __restrict__ as_out,
                             float* __restrict__ ad_out,
                             int n_nodes, int heads)
{
    int gid  = blockIdx.x * blockDim.x + threadIdx.x;
    int warp = gid >> 5;
    int lane = gid & 31;
    int total = n_nodes * heads;
    if (warp >= total) return;
    int n  = warp / heads;
    int hd = warp % heads;
    const float* row = h + (size_t)n * heads * 64 + hd * 64;
    float x0 = row[lane], x1 = row[lane + 32];
    float s = x0 * a_src[hd * 64 + lane] + x1 * a_src[hd * 64 + lane + 32];
    float d = x0 * a_dst[hd * 64 + lane] + x1 * a_dst[hd * 64 + lane + 32];
#pragma unroll
    for (int o = 16; o > 0; o >>= 1) {
        s += __shfl_down_sync(FULLM, s, o);
        d += __shfl_down_sync(FULLM, d, o);
    }
    if (lane == 0) { as_out[warp] = s; ad_out[warp] = d; }
}

__device__ __forceinline__ float lexp(float e) {
    e = e > 0.f ? e : SLOPE * e;
    return __expf(e);
}

// ---------------- layer-1 fused softmax + gather (fp16 payload) -------------
__global__ void gather1_kernel(const int* __restrict__ roff,
                               const int* __restrict__ csr,
                               const float* __restrict__ as_in,
                               const float* __restrict__ ad_in,
                               const __half* __restrict__ h16,
                               const float* __restrict__ bias,
                               float* __restrict__ out)
{
    int warp = (blockIdx.x * blockDim.x + threadIdx.x) >> 5;
    int lane = threadIdx.x & 31;
    if (warp >= NNODES) return;
    const int d = warp;
    const int beg = roff[d], end = roff[d + 1];

    float4 ad4 = *(const float4*)(ad_in + (size_t)d * 4);

    float4 ws = make_float4(0.f, 0.f, 0.f, 0.f);
    for (int j = beg + lane; j < end; j += 32) {
        int s = csr[j];
        float4 a = *(const float4*)(as_in + (size_t)s * 4);
        ws.x += lexp(a.x + ad4.x);
        ws.y += lexp(a.y + ad4.y);
        ws.z += lexp(a.z + ad4.z);
        ws.w += lexp(a.w + ad4.w);
    }
    if (lane == 0) {
        float4 a = *(const float4*)(as_in + (size_t)d * 4);
        ws.x += lexp(a.x + ad4.x);
        ws.y += lexp(a.y + ad4.y);
        ws.z += lexp(a.z + ad4.z);
        ws.w += lexp(a.w + ad4.w);
    }
#pragma unroll
    for (int o = 16; o > 0; o >>= 1) {
        ws.x += __shfl_xor_sync(FULLM, ws.x, o);
        ws.y += __shfl_xor_sync(FULLM, ws.y, o);
        ws.z += __shfl_xor_sync(FULLM, ws.z, o);
        ws.w += __shfl_xor_sync(FULLM, ws.w, o);
    }
    const int hidx = lane >> 3;
    float wsum = (hidx == 0) ? ws.x : (hidx == 1) ? ws.y : (hidx == 2) ? ws.z : ws.w;
    float inv  = 1.f / (wsum + 1e-16f);
    float adh  = (hidx == 0) ? ad4.x : (hidx == 1) ? ad4.y : (hidx == 2) ? ad4.z : ad4.w;

    float acc[8];
#pragma unroll
    for (int k = 0; k < 8; k++) acc[k] = 0.f;

#define ACCUM1(w, q)                                                    \
    {                                                                   \
        const __half2* hp = (const __half2*)&(q);                       \
        float2 f0 = __half22float2(hp[0]);                              \
        float2 f1 = __half22float2(hp[1]);                              \
        float2 f2 = __half22float2(hp[2]);                              \
        float2 f3 = __half22float2(hp[3]);                              \
        acc[0] = fmaf(w, f0.x, acc[0]); acc[1] = fmaf(w, f0.y, acc[1]); \
        acc[2] = fmaf(w, f1.x, acc[2]); acc[3] = fmaf(w, f1.y, acc[3]); \
        acc[4] = fmaf(w, f2.x, acc[4]); acc[5] = fmaf(w, f2.y, acc[5]); \
        acc[6] = fmaf(w, f3.x, acc[6]); acc[7] = fmaf(w, f3.y, acc[7]); \
    }

    for (int j0 = beg; j0 < end; j0 += 32) {
        int cnt = min(32, end - j0);
        int my = (lane < cnt) ? csr[j0 + lane] : 0;
        int t = 0;
        for (; t + 3 < cnt; t += 4) {
            int s0 = __shfl_sync(FULLM, my, t);
            int s1 = __shfl_sync(FULLM, my, t + 1);
            int s2 = __shfl_sync(FULLM, my, t + 2);
            int s3 = __shfl_sync(FULLM, my, t + 3);
            float w0 = as_in[(size_t)s0 * 4 + hidx];
            float w1 = as_in[(size_t)s1 * 4 + hidx];
            float w2 = as_in[(size_t)s2 * 4 + hidx];
            float w3 = as_in[(size_t)s3 * 4 + hidx];
            uint4 q0 = *(const uint4*)(h16 + (size_t)s0 * F1 + lane * 8);
            uint4 q1 = *(const uint4*)(h16 + (size_t)s1 * F1 + lane * 8);
            uint4 q2 = *(const uint4*)(h16 + (size_t)s2 * F1 + lane * 8);
            uint4 q3 = *(const uint4*)(h16 + (size_t)s3 * F1 + lane * 8);
            w0 = lexp(w0 + adh); w1 = lexp(w1 + adh);
            w2 = lexp(w2 + adh); w3 = lexp(w3 + adh);
            ACCUM1(w0, q0); ACCUM1(w1, q1); ACCUM1(w2, q2); ACCUM1(w3, q3);
        }
        for (; t < cnt; t++) {
            int s0 = __shfl_sync(FULLM, my, t);
            float w0 = lexp(as_in[(size_t)s0 * 4 + hidx] + adh);
            uint4 q0 = *(const uint4*)(h16 + (size_t)s0 * F1 + lane * 8);
            ACCUM1(w0, q0);
        }
    }
    {   // self loop
        float w0 = lexp(as_in[(size_t)d * 4 + hidx] + adh);
        uint4 q0 = *(const uint4*)(h16 + (size_t)d * F1 + lane * 8);
        ACCUM1(w0, q0);
    }
#undef ACCUM1

    size_t base = (size_t)d * F1 + lane * 8;
#pragma unroll
    for (int k = 0; k < 8; k++) {
        float v = acc[k] * inv + bias[lane * 8 + k];
        out[base + k] = v > 0.f ? v : expm1f(v);
    }
}

// ---------------- layer-2 fused softmax + gather (fp16 payload) -------------
__global__ void gather2_kernel(const int* __restrict__ roff,
                               const int* __restrict__ csr,
                               const float* __restrict__ as_in,
                               const float* __restrict__ ad_in,
                               const __half* __restrict__ h16,
                               const float* __restrict__ bias,
                               float* __restrict__ out)
{
    int warp = (blockIdx.x * blockDim.x + threadIdx.x) >> 5;
    int lane = threadIdx.x & 31;
    if (warp >= NNODES) return;
    const int d = warp;
    const int beg = roff[d], end = roff[d + 1];

    float add = ad_in[d];

    float ws = 0.f;
    for (int j = beg + lane; j < end; j += 32) {
        int s = csr[j];
        ws += lexp(as_in[s] + add);
    }
    if (lane == 0) ws += lexp(as_in[d] + add);
#pragma unroll
    for (int o = 16; o > 0; o >>= 1) ws += __shfl_xor_sync(FULLM, ws, o);
    float inv = 1.f / (ws + 1e-16f);

    float2 acc = make_float2(0.f, 0.f);
    for (int j0 = beg; j0 < end; j0 += 32) {
        int cnt = min(32, end - j0);
        int my = (lane < cnt) ? csr[j0 + lane] : 0;
        int t = 0;
        for (; t + 3 < cnt; t += 4) {
            int s0 = __shfl_sync(FULLM, my, t);
            int s1 = __shfl_sync(FULLM, my, t + 1);
            int s2 = __shfl_sync(FULLM, my, t + 2);
            int s3 = __shfl_sync(FULLM, my, t + 3);
            float w0 = as_in[s0], w1 = as_in[s1], w2 = as_in[s2], w3 = as_in[s3];
            __half2 v0 = *(const __half2*)(h16 + (size_t)s0 * HD + lane * 2);
            __half2 v1 = *(const __half2*)(h16 + (size_t)s1 * HD + lane * 2);
            __half2 v2 = *(const __half2*)(h16 + (size_t)s2 * HD + lane * 2);
            __half2 v3 = *(const __half2*)(h16 + (size_t)s3 * HD + lane * 2);
            w0 = lexp(w0 + add); w1 = lexp(w1 + add);
            w2 = lexp(w2 + add); w3 = lexp(w3 + add);
            float2 f0 = __half22float2(v0), f1 = __half22float2(v1);
            float2 f2 = __half22float2(v2), f3 = __half22float2(v3);
            acc.x = fmaf(w0, f0.x, acc.x); acc.y = fmaf(w0, f0.y, acc.y);
            acc.x = fmaf(w1, f1.x, acc.x); acc.y = fmaf(w1, f1.y, acc.y);
            acc.x = fmaf(w2, f2.x, acc.x); acc.y = fmaf(w2, f2.y, acc.y);
            acc.x = fmaf(w3, f3.x, acc.x); acc.y = fmaf(w3, f3.y, acc.y);
        }
        for (; t < cnt; t++) {
            int s0 = __shfl_sync(FULLM, my, t);
            float w0 = lexp(as_in[s0] + add);
            float2 u = __half22float2(*(const __half2*)(h16 + (size_t)s0 * HD + lane * 2));
            acc.x = fmaf(w0, u.x, acc.x); acc.y = fmaf(w0, u.y, acc.y);
        }
    }
    {
        float w0 = lexp(as_in[d] + add);
        float2 u = __half22float2(*(const __half2*)(h16 + (size_t)d * HD + lane * 2));
        acc.x = fmaf(w0, u.x, acc.x); acc.y = fmaf(w0, u.y, acc.y);
    }

    out[(size_t)d * HD + lane * 2 + 0] = acc.x * inv + bias[lane * 2 + 0];
    out[(size_t)d * HD + lane * 2 + 1] = acc.y * inv + bias[lane * 2 + 1];
}

// ---------------- launch ----------------------------------------------------
extern "C" void kernel_launch(void* const* d_in, const int* in_sizes, int n_in,
                              void* d_out, int out_size)
{
    const float* x     = (const float*)d_in[0];
    const int*   ei    = (const int*)d_in[1];     // int32 (JAX x64 disabled)
    const float* W1    = (const float*)d_in[2];
    const float* asrc1 = (const float*)d_in[3];
    const float* adst1 = (const float*)d_in[4];
    const float* b1    = (const float*)d_in[5];
    const float* W2    = (const float*)d_in[6];
    const float* asrc2 = (const float*)d_in[7];
    const float* adst2 = (const float*)d_in[8];
    const float* b2    = (const float*)d_in[9];
    float*       out   = (float*)d_out;

    int E = in_sizes[1] / 2;
    if (E > EMAX) E = EMAX;
    const int* src = ei;
    const int* dst = ei + E;

    float *h1, *o1, *h2, *as1, *ad1, *as2, *ad2;
    __half *h1h, *h2h;
    int *deg, *fill, *roff, *csr;
    cudaGetSymbolAddress((void**)&h1,   g_h1);
    cudaGetSymbolAddress((void**)&h1h,  g_h1h);
    cudaGetSymbolAddress((void**)&o1,   g_o1);
    cudaGetSymbolAddress((void**)&h2,   g_h2);
    cudaGetSymbolAddress((void**)&h2h,  g_h2h);
    cudaGetSymbolAddress((void**)&as1,  g_as1);
    cudaGetSymbolAddress((void**)&ad1,  g_ad1);
    cudaGetSymbolAddress((void**)&as2,  g_as2);
    cudaGetSymbolAddress((void**)&ad2,  g_ad2);
    cudaGetSymbolAddress((void**)&deg,  g_deg);
    cudaGetSymbolAddress((void**)&fill, g_fill);
    cudaGetSymbolAddress((void**)&roff, g_roff);
    cudaGetSymbolAddress((void**)&csr,  g_csr_src);

    // ---- CSR build (reused by both layers) ----
    cudaMemsetAsync(deg,  0, NNODES * sizeof(int));
    cudaMemsetAsync(fill, 0, NNODES * sizeof(int));
    hist_kernel<<<(E + 255) / 256, 256>>>(dst, E, deg);
    scan_kernel<<<1, 1024>>>(deg, roff);
    scatter_kernel<<<(E + 255) / 256, 256>>>(src, dst, E, roff, fill, csr);

    // ---- layer 1 ----
    {
        dim3 grid(F1 / 128, (NNODES + 127) / 128);
        hgemm_split_kernel<128, 128, 64, 32><<<grid, 256>>>(x, W1, h1, h1h, NNODES, F1, FIN);
    }
    alpha_kernel<<<(NNODES * HH + 7) / 8, 256>>>(h1, asrc1, adst1, as1, ad1, NNODES, HH);
    gather1_kernel<<<(NNODES + 7) / 8, 256>>>(roff, csr, as1, ad1, h1h, b1, o1);

    // ---- layer 2 ----
    {
        dim3 grid(1, (NNODES + 127) / 128);
        hgemm_split_kernel<128, 64, 64, 16><<<grid, 256>>>(o1, W2, h2, h2h, NNODES, HD, F1);
    }
    alpha_kernel<<<(NNODES + 7) / 8, 256>>>(h2, asrc2, adst2, as2, ad2, NNODES, 1);
    gather2_kernel<<<(NNODES + 7) / 8, 256>>>(roff, csr, as2, ad2, h2h, b2, out);
}

// round 8
// speedup vs baseline: 1.0348x; 1.0348x over previous
#include <cuda_runtime.h>
#include <cuda_fp16.h>
#include <math.h>

#define NNODES 50000
#define FIN    256
#define HH     4
#define HD     64
#define F1     (HH*HD)          // 256
#define EMAX   1600000
#define SLOPE  0.2f
#define FULLM  0xffffffffu

// ---------------- scratch (device globals) ----------------------------------
__device__ float  g_h1[(size_t)NNODES * F1];     // 51.2 MB (fp32, for alpha)
__device__ __half g_h1h[(size_t)NNODES * F1];    // 25.6 MB (fp16, for gather)
__device__ float  g_o1[(size_t)NNODES * F1];     // 51.2 MB
__device__ float  g_h2[(size_t)NNODES * HD];     // 12.8 MB
__device__ __half g_h2h[(size_t)NNODES * HD];    // 6.4 MB
__device__ float  g_as1[NNODES * HH];
__device__ float  g_ad1[NNODES * HH];
__device__ float  g_as2[NNODES];
__device__ float  g_ad2[NNODES];
__device__ int    g_deg[NNODES];
__device__ int    g_fill[NNODES];
__device__ int    g_roff[NNODES + 1];
__device__ int    g_csr_src[EMAX];               // 6.4 MB

// ---------------- tf32 helpers ----------------------------------------------
__device__ __forceinline__ unsigned f2tf(float f) {
    unsigned u;
    asm("cvt.rna.tf32.f32 %0, %1;" : "=r"(u) : "f"(f));
    return u;
}
__device__ __forceinline__ void mma_tf32(float* c, const unsigned* a, const unsigned* b) {
    asm volatile(
        "mma.sync.aligned.m16n8k8.row.col.f32.tf32.tf32.f32 "
        "{%0,%1,%2,%3}, {%4,%5,%6,%7}, {%8,%9}, {%0,%1,%2,%3};"
        : "+f"(c[0]), "+f"(c[1]), "+f"(c[2]), "+f"(c[3])
        : "r"(a[0]), "r"(a[1]), "r"(a[2]), "r"(a[3]), "r"(b[0]), "r"(b[1]));
}

// ------------- split-tf32 GEMM (fp32 accuracy): C[M,N]=A[M,K]@B[K,N] --------
// Writes fp32 C and an fp16 mirror C16.
template<int BM, int BN, int WM, int WN>
__global__ void tf32_gemm_kernel(const float* __restrict__ A,
                                 const float* __restrict__ B,
                                 float* __restrict__ C,
                                 __half* __restrict__ C16,
                                 int M, int N, int K)
{
    constexpr int BK = 16;
    constexpr int WARPS_M = BM / WM;
    constexpr int WARPS_N = BN / WN;
    constexpr int THREADS = WARPS_M * WARPS_N * 32;
    constexpr int MT = WM / 16;
    constexpr int NT = WN / 8;

    __shared__ unsigned AsH[BM][BK + 4];
    __shared__ unsigned AsL[BM][BK + 4];
    __shared__ unsigned BsH[BK][BN + 8];
    __shared__ unsigned BsL[BK][BN + 8];

    const int tid  = threadIdx.x;
    const int lane = tid & 31;
    const int wid  = tid >> 5;
    const int wm   = wid % WARPS_M;
    const int wn   = wid / WARPS_M;
    const int gid  = lane >> 2;
    const int tg   = lane & 3;
    const int row0 = blockIdx.y * BM;
    const int col0 = blockIdx.x * BN;

    float acc[MT][NT][4];
#pragma unroll
    for (int i = 0; i < MT; i++)
#pragma unroll
        for (int j = 0; j < NT; j++)
#pragma unroll
            for (int r = 0; r < 4; r++) acc[i][j][r] = 0.f;

    for (int k0 = 0; k0 < K; k0 += BK) {
#pragma unroll
        for (int i = tid; i < BM * (BK / 4); i += THREADS) {
            int m  = i / (BK / 4);
            int kq = (i % (BK / 4)) * 4;
            float4 v = make_float4(0.f, 0.f, 0.f, 0.f);
            if (row0 + m < M)
                v = *(const float4*)&A[(size_t)(row0 + m) * K + k0 + kq];
            float f[4] = {v.x, v.y, v.z, v.w};
#pragma unroll
            for (int j = 0; j < 4; j++) {
                unsigned h = f2tf(f[j]);
                AsH[m][kq + j] = h;
                AsL[m][kq + j] = f2tf(f[j] - __uint_as_float(h));
            }
        }
#pragma unroll
        for (int i = tid; i < BK * (BN / 4); i += THREADS) {
            int kk = i / (BN / 4);
            int nq = (i % (BN / 4)) * 4;
            float4 v = *(const float4*)&B[(size_t)(k0 + kk) * N + col0 + nq];
            float f[4] = {v.x, v.y, v.z, v.w};
#pragma unroll
            for (int j = 0; j < 4; j++) {
                unsigned h = f2tf(f[j]);
                BsH[kk][nq + j] = h;
                BsL[kk][nq + j] = f2tf(f[j] - __uint_as_float(h));
            }
        }
        __syncthreads();

#pragma unroll
        for (int ks = 0; ks < BK / 8; ks++) {
            const int kb = ks * 8;
            unsigned aH[MT][4], aL[MT][4], bH[NT][2], bL[NT][2];
#pragma unroll
            for (int mt = 0; mt < MT; mt++) {
                int mr = wm * WM + mt * 16 + gid;
                aH[mt][0] = AsH[mr    ][kb + tg];
                aH[mt][1] = AsH[mr + 8][kb + tg];
                aH[mt][2] = AsH[mr    ][kb + tg + 4];
                aH[mt][3] = AsH[mr + 8][kb + tg + 4];
                aL[mt][0] = AsL[mr    ][kb + tg];
                aL[mt][1] = AsL[mr + 8][kb + tg];
                aL[mt][2] = AsL[mr    ][kb + tg + 4];
                aL[mt][3] = AsL[mr + 8][kb + tg + 4];
            }
#pragma unroll
            for (int nt = 0; nt < NT; nt++) {
                int nc = wn * WN + nt * 8 + gid;
                bH[nt][0] = BsH[kb + tg    ][nc];
                bH[nt][1] = BsH[kb + tg + 4][nc];
                bL[nt][0] = BsL[kb + tg    ][nc];
                bL[nt][1] = BsL[kb + tg + 4][nc];
            }
#pragma unroll
            for (int mt = 0; mt < MT; mt++)
#pragma unroll
                for (int nt = 0; nt < NT; nt++) {
                    mma_tf32(acc[mt][nt], aH[mt], bH[nt]);
                    mma_tf32(acc[mt][nt], aH[mt], bL[nt]);
                    mma_tf32(acc[mt][nt], aL[mt], bH[nt]);
                }
        }
        __syncthreads();
    }

#pragma unroll
    for (int mt = 0; mt < MT; mt++) {
        int m0 = row0 + wm * WM + mt * 16 + gid;
#pragma unroll
        for (int nt = 0; nt < NT; nt++) {
            int nc = col0 + wn * WN + nt * 8 + tg * 2;
            if (m0 < M) {
                *(float2*)&C[(size_t)m0 * N + nc] =
                    make_float2(acc[mt][nt][0], acc[mt][nt][1]);
                *(__half2*)&C16[(size_t)m0 * N + nc] =
                    __floats2half2_rn(acc[mt][nt][0], acc[mt][nt][1]);
            }
            if (m0 + 8 < M) {
                *(float2*)&C[(size_t)(m0 + 8) * N + nc] =
                    make_float2(acc[mt][nt][2], acc[mt][nt][3]);
                *(__half2*)&C16[(size_t)(m0 + 8) * N + nc] =
                    __floats2half2_rn(acc[mt][nt][2], acc[mt][nt][3]);
            }
        }
    }
}

// ---------------- CSR build -------------------------------------------------
__global__ void hist_kernel(const int* __restrict__ dst, int E, int* __restrict__ deg)
{
    int e = blockIdx.x * blockDim.x + threadIdx.x;
    if (e >= E) return;
    int d = dst[e];
    if ((unsigned)d < NNODES) atomicAdd(&deg[d], 1);
}

__global__ void scan_kernel(const int* __restrict__ deg, int* __restrict__ roff)
{
    __shared__ int part[1024];
    const int tid = threadIdx.x;
    const int CH = (NNODES + 1023) / 1024;
    const int base = tid * CH;
    int s = 0;
    for (int i = 0; i < CH; i++) {
        int idx = base + i;
        if (idx < NNODES) s += deg[idx];
    }
    part[tid] = s;
    __syncthreads();
    for (int off = 1; off < 1024; off <<= 1) {
        int v = 0;
        if (tid >= off) v = part[tid - off];
        __syncthreads();
        if (tid >= off) part[tid] += v;
        __syncthreads();
    }
    int run = (tid == 0) ? 0 : part[tid - 1];
    for (int i = 0; i < CH; i++) {
        int idx = base + i;
        if (idx < NNODES) { roff[idx] = run; run += deg[idx]; }
    }
    if (tid == 1023) roff[NNODES] = run;
}

__global__ void scatter_kernel(const int* __restrict__ src, const int* __restrict__ dst,
                               int E, const int* __restrict__ roff,
                               int* __restrict__ fill, int* __restrict__ csr)
{
    int e = blockIdx.x * blockDim.x + threadIdx.x;
    if (e >= E) return;
    int d = dst[e], s = src[e];
    if ((unsigned)d >= NNODES || (unsigned)s >= NNODES) return;
    int p = atomicAdd(&fill[d], 1);
    csr[roff[d] + p] = s;
}

// ---------------- per-node attention logits (fp32 h) ------------------------
__global__ void alpha_kernel(const float* __restrict__ h,
                             const float* __restrict__ a_src,
                             const float* __restrict__ a_dst,
                             float* __restrict__ as_out,
                             float* __restrict__ ad_out,
                             int n_nodes, int heads)
{
    int gid  = blockIdx.x * blockDim.x + threadIdx.x;
    int warp = gid >> 5;
    int lane = gid & 31;
    int total = n_nodes * heads;
    if (warp >= total) return;
    int n  = warp / heads;
    int hd = warp % heads;
    const float* row = h + (size_t)n * heads * 64 + hd * 64;
    float x0 = row[lane], x1 = row[lane + 32];
    float s = x0 * a_src[hd * 64 + lane] + x1 * a_src[hd * 64 + lane + 32];
    float d = x0 * a_dst[hd * 64 + lane] + x1 * a_dst[hd * 64 + lane + 32];
#pragma unroll
    for (int o = 16; o > 0; o >>= 1) {
        s += __shfl_down_sync(FULLM, s, o);
        d += __shfl_down_sync(FULLM, d, o);
    }
    if (lane == 0) { as_out[warp] = s; ad_out[warp] = d; }
}

__device__ __forceinline__ float lexp(float e) {
    e = e > 0.f ? e : SLOPE * e;
    return __expf(e);
}

// ---------------- layer-1 fused softmax + gather (fp16 payload) -------------
__global__ void gather1_kernel(const int* __restrict__ roff,
                               const int* __restrict__ csr,
                               const float* __restrict__ as_in,
                               const float* __restrict__ ad_in,
                               const __half* __restrict__ h16,
                               const float* __restrict__ bias,
                               float* __restrict__ out)
{
    int warp = (blockIdx.x * blockDim.x + threadIdx.x) >> 5;
    int lane = threadIdx.x & 31;
    if (warp >= NNODES) return;
    const int d = warp;
    const int beg = roff[d], end = roff[d + 1];

    float4 ad4 = *(const float4*)(ad_in + (size_t)d * 4);

    float4 ws = make_float4(0.f, 0.f, 0.f, 0.f);
    for (int j = beg + lane; j < end; j += 32) {
        int s = csr[j];
        float4 a = *(const float4*)(as_in + (size_t)s * 4);
        ws.x += lexp(a.x + ad4.x);
        ws.y += lexp(a.y + ad4.y);
        ws.z += lexp(a.z + ad4.z);
        ws.w += lexp(a.w + ad4.w);
    }
    if (lane == 0) {
        float4 a = *(const float4*)(as_in + (size_t)d * 4);
        ws.x += lexp(a.x + ad4.x);
        ws.y += lexp(a.y + ad4.y);
        ws.z += lexp(a.z + ad4.z);
        ws.w += lexp(a.w + ad4.w);
    }
#pragma unroll
    for (int o = 16; o > 0; o >>= 1) {
        ws.x += __shfl_xor_sync(FULLM, ws.x, o);
        ws.y += __shfl_xor_sync(FULLM, ws.y, o);
        ws.z += __shfl_xor_sync(FULLM, ws.z, o);
        ws.w += __shfl_xor_sync(FULLM, ws.w, o);
    }
    const int hidx = lane >> 3;
    float wsum = (hidx == 0) ? ws.x : (hidx == 1) ? ws.y : (hidx == 2) ? ws.z : ws.w;
    float inv  = 1.f / (wsum + 1e-16f);
    float adh  = (hidx == 0) ? ad4.x : (hidx == 1) ? ad4.y : (hidx == 2) ? ad4.z : ad4.w;

    float acc[8];
#pragma unroll
    for (int k = 0; k < 8; k++) acc[k] = 0.f;

#define ACCUM1(w, q)                                                    \
    {                                                                   \
        const __half2* hp = (const __half2*)&(q);                       \
        float2 f0 = __half22float2(hp[0]);                              \
        float2 f1 = __half22float2(hp[1]);                              \
        float2 f2 = __half22float2(hp[2]);                              \
        float2 f3 = __half22float2(hp[3]);                              \
        acc[0] = fmaf(w, f0.x, acc[0]); acc[1] = fmaf(w, f0.y, acc[1]); \
        acc[2] = fmaf(w, f1.x, acc[2]); acc[3] = fmaf(w, f1.y, acc[3]); \
        acc[4] = fmaf(w, f2.x, acc[4]); acc[5] = fmaf(w, f2.y, acc[5]); \
        acc[6] = fmaf(w, f3.x, acc[6]); acc[7] = fmaf(w, f3.y, acc[7]); \
    }

    for (int j0 = beg; j0 < end; j0 += 32) {
        int cnt = min(32, end - j0);
        int my = (lane < cnt) ? csr[j0 + lane] : 0;
        int t = 0;
        for (; t + 3 < cnt; t += 4) {
            int s0 = __shfl_sync(FULLM, my, t);
            int s1 = __shfl_sync(FULLM, my, t + 1);
            int s2 = __shfl_sync(FULLM, my, t + 2);
            int s3 = __shfl_sync(FULLM, my, t + 3);
            float w0 = as_in[(size_t)s0 * 4 + hidx];
            float w1 = as_in[(size_t)s1 * 4 + hidx];
            float w2 = as_in[(size_t)s2 * 4 + hidx];
            float w3 = as_in[(size_t)s3 * 4 + hidx];
            uint4 q0 = *(const uint4*)(h16 + (size_t)s0 * F1 + lane * 8);
            uint4 q1 = *(const uint4*)(h16 + (size_t)s1 * F1 + lane * 8);
            uint4 q2 = *(const uint4*)(h16 + (size_t)s2 * F1 + lane * 8);
            uint4 q3 = *(const uint4*)(h16 + (size_t)s3 * F1 + lane * 8);
            w0 = lexp(w0 + adh); w1 = lexp(w1 + adh);
            w2 = lexp(w2 + adh); w3 = lexp(w3 + adh);
            ACCUM1(w0, q0); ACCUM1(w1, q1); ACCUM1(w2, q2); ACCUM1(w3, q3);
        }
        for (; t < cnt; t++) {
            int s0 = __shfl_sync(FULLM, my, t);
            float w0 = lexp(as_in[(size_t)s0 * 4 + hidx] + adh);
            uint4 q0 = *(const uint4*)(h16 + (size_t)s0 * F1 + lane * 8);
            ACCUM1(w0, q0);
        }
    }
    {   // self loop
        float w0 = lexp(as_in[(size_t)d * 4 + hidx] + adh);
        uint4 q0 = *(const uint4*)(h16 + (size_t)d * F1 + lane * 8);
        ACCUM1(w0, q0);
    }
#undef ACCUM1

    size_t base = (size_t)d * F1 + lane * 8;
#pragma unroll
    for (int k = 0; k < 8; k++) {
        float v = acc[k] * inv + bias[lane * 8 + k];
        out[base + k] = v > 0.f ? v : expm1f(v);
    }
}

// ---------------- layer-2 fused softmax + gather (fp16 payload) -------------
__global__ void gather2_kernel(const int* __restrict__ roff,
                               const int* __restrict__ csr,
                               const float* __restrict__ as_in,
                               const float* __restrict__ ad_in,
                               const __half* __restrict__ h16,
                               const float* __restrict__ bias,
                               float* __restrict__ out)
{
    int warp = (blockIdx.x * blockDim.x + threadIdx.x) >> 5;
    int lane = threadIdx.x & 31;
    if (warp >= NNODES) return;
    const int d = warp;
    const int beg = roff[d], end = roff[d + 1];

    float add = ad_in[d];

    float ws = 0.f;
    for (int j = beg + lane; j < end; j += 32) {
        int s = csr[j];
        ws += lexp(as_in[s] + add);
    }
    if (lane == 0) ws += lexp(as_in[d] + add);
#pragma unroll
    for (int o = 16; o > 0; o >>= 1) ws += __shfl_xor_sync(FULLM, ws, o);
    float inv = 1.f / (ws + 1e-16f);

    float2 acc = make_float2(0.f, 0.f);
    for (int j0 = beg; j0 < end; j0 += 32) {
        int cnt = min(32, end - j0);
        int my = (lane < cnt) ? csr[j0 + lane] : 0;
        int t = 0;
        for (; t + 3 < cnt; t += 4) {
            int s0 = __shfl_sync(FULLM, my, t);
            int s1 = __shfl_sync(FULLM, my, t + 1);
            int s2 = __shfl_sync(FULLM, my, t + 2);
            int s3 = __shfl_sync(FULLM, my, t + 3);
            float w0 = as_in[s0], w1 = as_in[s1], w2 = as_in[s2], w3 = as_in[s3];
            __half2 v0 = *(const __half2*)(h16 + (size_t)s0 * HD + lane * 2);
            __half2 v1 = *(const __half2*)(h16 + (size_t)s1 * HD + lane * 2);
            __half2 v2 = *(const __half2*)(h16 + (size_t)s2 * HD + lane * 2);
            __half2 v3 = *(const __half2*)(h16 + (size_t)s3 * HD + lane * 2);
            w0 = lexp(w0 + add); w1 = lexp(w1 + add);
            w2 = lexp(w2 + add); w3 = lexp(w3 + add);
            float2 f0 = __half22float2(v0), f1 = __half22float2(v1);
            float2 f2 = __half22float2(v2), f3 = __half22float2(v3);
            acc.x = fmaf(w0, f0.x, acc.x); acc.y = fmaf(w0, f0.y, acc.y);
            acc.x = fmaf(w1, f1.x, acc.x); acc.y = fmaf(w1, f1.y, acc.y);
            acc.x = fmaf(w2, f2.x, acc.x); acc.y = fmaf(w2, f2.y, acc.y);
            acc.x = fmaf(w3, f3.x, acc.x); acc.y = fmaf(w3, f3.y, acc.y);
        }
        for (; t < cnt; t++) {
            int s0 = __shfl_sync(FULLM, my, t);
            float w0 = lexp(as_in[s0] + add);
            float2 u = __half22float2(*(const __half2*)(h16 + (size_t)s0 * HD + lane * 2));
            acc.x = fmaf(w0, u.x, acc.x); acc.y = fmaf(w0, u.y, acc.y);
        }
    }
    {
        float w0 = lexp(as_in[d] + add);
        float2 u = __half22float2(*(const __half2*)(h16 + (size_t)d * HD + lane * 2));
        acc.x = fmaf(w0, u.x, acc.x); acc.y = fmaf(w0, u.y, acc.y);
    }

    out[(size_t)d * HD + lane * 2 + 0] = acc.x * inv + bias[lane * 2 + 0];
    out[(size_t)d * HD + lane * 2 + 1] = acc.y * inv + bias[lane * 2 + 1];
}

// ---------------- launch ----------------------------------------------------
extern "C" void kernel_launch(void* const* d_in, const int* in_sizes, int n_in,
                              void* d_out, int out_size)
{
    const float* x     = (const float*)d_in[0];
    const int*   ei    = (const int*)d_in[1];     // int32 (JAX x64 disabled)
    const float* W1    = (const float*)d_in[2];
    const float* asrc1 = (const float*)d_in[3];
    const float* adst1 = (const float*)d_in[4];
    const float* b1    = (const float*)d_in[5];
    const float* W2    = (const float*)d_in[6];
    const float* asrc2 = (const float*)d_in[7];
    const float* adst2 = (const float*)d_in[8];
    const float* b2    = (const float*)d_in[9];
    float*       out   = (float*)d_out;

    int E = in_sizes[1] / 2;
    if (E > EMAX) E = EMAX;
    const int* src = ei;
    const int* dst = ei + E;

    float *h1, *o1, *h2, *as1, *ad1, *as2, *ad2;
    __half *h1h, *h2h;
    int *deg, *fill, *roff, *csr;
    cudaGetSymbolAddress((void**)&h1,   g_h1);
    cudaGetSymbolAddress((void**)&h1h,  g_h1h);
    cudaGetSymbolAddress((void**)&o1,   g_o1);
    cudaGetSymbolAddress((void**)&h2,   g_h2);
    cudaGetSymbolAddress((void**)&h2h,  g_h2h);
    cudaGetSymbolAddress((void**)&as1,  g_as1);
    cudaGetSymbolAddress((void**)&ad1,  g_ad1);
    cudaGetSymbolAddress((void**)&as2,  g_as2);
    cudaGetSymbolAddress((void**)&ad2,  g_ad2);
    cudaGetSymbolAddress((void**)&deg,  g_deg);
    cudaGetSymbolAddress((void**)&fill, g_fill);
    cudaGetSymbolAddress((void**)&roff, g_roff);
    cudaGetSymbolAddress((void**)&csr,  g_csr_src);

    // ---- CSR build (reused by both layers) ----
    cudaMemsetAsync(deg,  0, NNODES * sizeof(int));
    cudaMemsetAsync(fill, 0, NNODES * sizeof(int));
    hist_kernel<<<(E + 255) / 256, 256>>>(dst, E, deg);
    scan_kernel<<<1, 1024>>>(deg, roff);
    scatter_kernel<<<(E + 255) / 256, 256>>>(src, dst, E, roff, fill, csr);

    // ---- layer 1 ----
    {
        dim3 grid(F1 / 128, (NNODES + 127) / 128);
        tf32_gemm_kernel<128, 128, 64, 32><<<grid, 256>>>(x, W1, h1, h1h, NNODES, F1, FIN);
    }
    alpha_kernel<<<(NNODES * HH + 7) / 8, 256>>>(h1, asrc1, adst1, as1, ad1, NNODES, HH);
    gather1_kernel<<<(NNODES + 7) / 8, 256>>>(roff, csr, as1, ad1, h1h, b1, o1);

    // ---- layer 2 ----
    {
        dim3 grid(1, (NNODES + 127) / 128);
        tf32_gemm_kernel<128, 64, 64, 16><<<grid, 256>>>(o1, W2, h2, h2h, NNODES, HD, F1);
    }
    alpha_kernel<<<(NNODES + 7) / 8, 256>>>(h2, asrc2, adst2, as2, ad2, NNODES, 1);
    gather2_kernel<<<(NNODES + 7) / 8, 256>>>(roff, csr, as2, ad2, h2h, b2, out);
}